// round 3
// baseline (speedup 1.0000x reference)
#include <cuda_runtime.h>
#include <cstdint>

// ============================================================================
// 20-qubit, depth-4 strongly-entangling circuit, batch 64, <Z_0> output.
// Fused into 8 full-state sweeps (2 per layer), in-place, single 512MB buffer.
//
// Index convention: state index i (20 bits), wire w <-> bit p = 19 - w
// (wire 0 = MSB, PennyLane convention). Batch-inner layout: g_state[i*64 + s].
//
// Pass 1: local = i-bits 9..19  (wires 0..10).  c bit j <-> i bit 9+j.
//         gates: Rot(w=0..10), CNOT(0,1)..(9,10).  Non-local r = i bits 0..8.
// Pass 2: local = i-bits 0..9 and bit 19 (wires 10..19 and 0).
//         c bit j (j<=9) <-> i bit j ; c bit 10 <-> i bit 19.
//         gates: Rot(11..19), CNOT(10,11)..(18,19), CNOT(19,0).
//         Non-local r = i bits 10..18.
//
// Each CTA: 2048 local configs x 4 samples = 8192 amps in 64KB smem.
// 256 threads, 32 amps (5 local bits) in registers per thread; 3 rounds per
// pass with smem transposes between rounds; all gates applied in registers.
// ============================================================================

#define NQ      20
#define BATCH   64
#define NSTATE  (1 << 20)

__device__ float2 g_state[(size_t)NSTATE * BATCH];   // 512 MB
__device__ float2 g_rotm[4 * 20 * 4];                // [layer][wire][m00,m01,m10,m11]
__device__ float2 g_cs[BATCH * 20];                  // (cos(x/2), sin(x/2)) per (s,w)

// ---------------------------------------------------------------------------
// Register-block gate primitives: A[32] covers 5 "k-bits".
// ---------------------------------------------------------------------------
template <int Q>
__device__ __forceinline__ void rotg(float2* A, const float2* m) {
    const float2 m00 = m[0], m01 = m[1], m10 = m[2], m11 = m[3];
#pragma unroll
    for (int k = 0; k < 32; k++) {
        if (k & (1 << Q)) continue;
        const int k1 = k | (1 << Q);
        const float2 a = A[k], b = A[k1];
        A[k].x  = m00.x * a.x - m00.y * a.y + m01.x * b.x - m01.y * b.y;
        A[k].y  = m00.x * a.y + m00.y * a.x + m01.x * b.y + m01.y * b.x;
        A[k1].x = m10.x * a.x - m10.y * a.y + m11.x * b.x - m11.y * b.y;
        A[k1].y = m10.x * a.y + m10.y * a.x + m11.x * b.y + m11.y * b.x;
    }
}

template <int QC, int QT>
__device__ __forceinline__ void cnotg(float2* A) {
#pragma unroll
    for (int k = 0; k < 32; k++) {
        if ((k & (1 << QC)) && !(k & (1 << QT))) {
            const int k1 = k | (1 << QT);
            const float2 t = A[k]; A[k] = A[k1]; A[k1] = t;
        }
    }
}

// ---------------------------------------------------------------------------
// Setup: precompute Rot matrices and RX cos/sin tables (tiny).
// ---------------------------------------------------------------------------
__global__ void setup_kernel(const float* __restrict__ x,
                             const float* __restrict__ params) {
    int t = blockIdx.x * blockDim.x + threadIdx.x;
    if (t < 80) {
        // t = layer*20 + wire
        float phi = params[t * 3 + 0];
        float th  = params[t * 3 + 1];
        float om  = params[t * 3 + 2];
        float ct, st;  sincosf(0.5f * th, &st, &ct);
        float ap = -0.5f * (phi + om);        // m00 = e^{i ap} ct
        float am =  0.5f * (phi - om);        // m01 = -e^{i am} st, m10 = e^{-i am} st
        float ca, sa;  sincosf(ap, &sa, &ca);
        float cb, sb;  sincosf(am, &sb, &cb);
        g_rotm[t * 4 + 0] = make_float2( ca * ct,  sa * ct);
        g_rotm[t * 4 + 1] = make_float2(-cb * st, -sb * st);
        g_rotm[t * 4 + 2] = make_float2( cb * st, -sb * st);
        g_rotm[t * 4 + 3] = make_float2( ca * ct, -sa * ct);
    }
    int u = t - 80;
    if (u >= 0 && u < BATCH * 20) {
        float c, s;  sincosf(0.5f * x[u], &s, &c);
        g_cs[u] = make_float2(c, s);   // bit0 amp = c ; bit1 amp = -i*s
    }
}

// multiply v by factor: bit==0 -> *cos ; bit==1 -> *(-i sin)
__device__ __forceinline__ float2 rx_factor(float2 v, float2 f, int bit) {
    if (bit) return make_float2(f.y * v.y, -f.y * v.x);
    return make_float2(f.x * v.x, f.x * v.y);
}

// ---------------------------------------------------------------------------
// Pass 1: local i-bits 9..19.  GEN=true generates the post-RX product state
// (layer 0) with no global read.
// Rounds (c-bit sets): A={6..10}, B={2..6}, C={0..4}.
// ---------------------------------------------------------------------------
template <bool GEN>
__global__ void __launch_bounds__(256, 2) pass1_kernel(int layer) {
    extern __shared__ float2 sm[];              // 8192 entries = 64KB, idx = c*4 + s2
    const int t     = threadIdx.x;
    const int s2    = t & 3;
    const int u     = t >> 2;                   // 6 bits: complement of round's 5 bits
    const int r     = blockIdx.x & 511;         // i bits 0..8
    const int sBase = (blockIdx.x >> 9) * 4;    // 16 sample groups
    const float2* rm = g_rotm + layer * 80;

    if (!GEN) {
#pragma unroll
        for (int it = 0; it < 32; it++) {
            int e = t + it * 256;
            int c = e >> 2, ss = e & 3;
            sm[e] = g_state[(((c << 9) | r) << 6) + sBase + ss];
        }
        __syncthreads();
    }

    float2 A[32];

    // ---- Round A: c = (k<<6) | u  (k-bit q <-> c-bit 6+q <-> wire 4-q) ----
    if (GEN) {
        const float2* csrow = g_cs + (sBase + s2) * 20;
        const int ifx = (u << 9) | r;           // i bits 0..14 (wires 19..5)
        float2 base = make_float2(1.f, 0.f);
#pragma unroll
        for (int p = 0; p < 15; p++)
            base = rx_factor(base, csrow[19 - p], (ifx >> p) & 1);
        float2 fw[5];
#pragma unroll
        for (int q = 0; q < 5; q++) fw[q] = csrow[4 - q];
#pragma unroll
        for (int k = 0; k < 32; k++) {
            float2 v = base;
#pragma unroll
            for (int q = 0; q < 5; q++) v = rx_factor(v, fw[q], (k >> q) & 1);
            A[k] = v;
        }
    } else {
#pragma unroll
        for (int k = 0; k < 32; k++) A[k] = sm[((((k << 6) | u)) << 2) | s2];
    }
    rotg<4>(A, rm + 0 * 4);   // Rot wire 0
    rotg<3>(A, rm + 1 * 4);   // wire 1
    rotg<2>(A, rm + 2 * 4);   // wire 2
    rotg<1>(A, rm + 3 * 4);   // wire 3
    rotg<0>(A, rm + 4 * 4);   // wire 4
    cnotg<4, 3>(A);           // CNOT(0,1)
    cnotg<3, 2>(A);           // CNOT(1,2)
    cnotg<2, 1>(A);           // CNOT(2,3)
    cnotg<1, 0>(A);           // CNOT(3,4)
#pragma unroll
    for (int k = 0; k < 32; k++) sm[((((k << 6) | u)) << 2) | s2] = A[k];
    __syncthreads();

    // ---- Round B: c = ((u>>2)<<7) | (k<<2) | (u&3)  (k q <-> c 2+q <-> wire 8-q)
#pragma unroll
    for (int k = 0; k < 32; k++) {
        int c = ((u >> 2) << 7) | (k << 2) | (u & 3);
        A[k] = sm[(c << 2) | s2];
    }
    rotg<3>(A, rm + 5 * 4);   // wire 5
    rotg<2>(A, rm + 6 * 4);   // wire 6
    rotg<1>(A, rm + 7 * 4);   // wire 7
    rotg<0>(A, rm + 8 * 4);   // wire 8
    cnotg<4, 3>(A);           // CNOT(4,5)
    cnotg<3, 2>(A);           // CNOT(5,6)
    cnotg<2, 1>(A);           // CNOT(6,7)
    cnotg<1, 0>(A);           // CNOT(7,8)
#pragma unroll
    for (int k = 0; k < 32; k++) {
        int c = ((u >> 2) << 7) | (k << 2) | (u & 3);
        sm[(c << 2) | s2] = A[k];
    }
    __syncthreads();

    // ---- Round C: c = (u<<5) | k  (k q <-> c q <-> wire 10-q) ----
#pragma unroll
    for (int k = 0; k < 32; k++) A[k] = sm[((((u << 5) | k)) << 2) | s2];
    rotg<1>(A, rm + 9 * 4);   // wire 9
    rotg<0>(A, rm + 10 * 4);  // wire 10
    cnotg<2, 1>(A);           // CNOT(8,9)
    cnotg<1, 0>(A);           // CNOT(9,10)
#pragma unroll
    for (int k = 0; k < 32; k++) sm[((((u << 5) | k)) << 2) | s2] = A[k];
    __syncthreads();

#pragma unroll
    for (int it = 0; it < 32; it++) {
        int e = t + it * 256;
        int c = e >> 2, ss = e & 3;
        g_state[(((c << 9) | r) << 6) + sBase + ss] = sm[e];
    }
}

// ---------------------------------------------------------------------------
// Pass 2: local = i-bits 0..9 + bit 19.  RED=true folds the <Z_0> reduction.
// c bit j (j<=9) <-> i bit j (wire 19-j) ; c bit 10 <-> i bit 19 (wire 0).
// Rounds (c-bit sets): A={5..9}, B={1..5}, C={0,1,8,9,10}.
// ---------------------------------------------------------------------------
template <bool RED>
__global__ void __launch_bounds__(256, 2) pass2_kernel(int layer, float* out) {
    extern __shared__ float2 sm[];
    const int t     = threadIdx.x;
    const int s2    = t & 3;
    const int u     = t >> 2;
    const int r     = blockIdx.x & 511;         // i bits 10..18
    const int sBase = (blockIdx.x >> 9) * 4;
    const float2* rm = g_rotm + layer * 80;

#pragma unroll
    for (int it = 0; it < 32; it++) {
        int e = t + it * 256;
        int c = e >> 2, ss = e & 3;
        int gi = ((c >> 10) << 19) | (r << 10) | (c & 1023);
        sm[e] = g_state[(gi << 6) + sBase + ss];
    }
    __syncthreads();

    float2 A[32];

    // ---- Round A: c = (u&31) | (k<<5) | ((u>>5)<<10)  (k q <-> j=5+q, wire 14-q)
#pragma unroll
    for (int k = 0; k < 32; k++) {
        int c = (u & 31) | (k << 5) | ((u >> 5) << 10);
        A[k] = sm[(c << 2) | s2];
    }
    rotg<3>(A, rm + 11 * 4);  // wire 11 (j=8)
    rotg<2>(A, rm + 12 * 4);  // wire 12
    rotg<1>(A, rm + 13 * 4);  // wire 13
    rotg<0>(A, rm + 14 * 4);  // wire 14
    cnotg<4, 3>(A);           // CNOT(10,11)
    cnotg<3, 2>(A);           // CNOT(11,12)
    cnotg<2, 1>(A);           // CNOT(12,13)
    cnotg<1, 0>(A);           // CNOT(13,14)
#pragma unroll
    for (int k = 0; k < 32; k++) {
        int c = (u & 31) | (k << 5) | ((u >> 5) << 10);
        sm[(c << 2) | s2] = A[k];
    }
    __syncthreads();

    // ---- Round B: c = (u&1) | (k<<1) | (((u>>1)&15)<<6) | ((u>>5)<<10)
    //      (k q <-> j=1+q, wire 18-q)
#pragma unroll
    for (int k = 0; k < 32; k++) {
        int c = (u & 1) | (k << 1) | (((u >> 1) & 15) << 6) | ((u >> 5) << 10);
        A[k] = sm[(c << 2) | s2];
    }
    rotg<3>(A, rm + 15 * 4);  // wire 15
    rotg<2>(A, rm + 16 * 4);  // wire 16
    rotg<1>(A, rm + 17 * 4);  // wire 17
    rotg<0>(A, rm + 18 * 4);  // wire 18
    cnotg<4, 3>(A);           // CNOT(14,15)
    cnotg<3, 2>(A);           // CNOT(15,16)
    cnotg<2, 1>(A);           // CNOT(16,17)
    cnotg<1, 0>(A);           // CNOT(17,18)
#pragma unroll
    for (int k = 0; k < 32; k++) {
        int c = (u & 1) | (k << 1) | (((u >> 1) & 15) << 6) | ((u >> 5) << 10);
        sm[(c << 2) | s2] = A[k];
    }
    __syncthreads();

    // ---- Round C: c = (k&3) | (u<<2) | ((k>>2)<<8)
    //      k0<->c0 (wire 19), k1<->c1 (wire 18), k2<->c8, k3<->c9, k4<->c10 (wire 0)
#pragma unroll
    for (int k = 0; k < 32; k++) {
        int c = (k & 3) | (u << 2) | ((k >> 2) << 8);
        A[k] = sm[(c << 2) | s2];
    }
    rotg<0>(A, rm + 19 * 4);  // wire 19
    cnotg<1, 0>(A);           // CNOT(18,19)
    cnotg<0, 4>(A);           // CNOT(19,0)  (control wire 19 = k0, target wire 0 = k4)

    if (RED) {
        float p = 0.f;
#pragma unroll
        for (int k = 0; k < 32; k++) {
            float m = A[k].x * A[k].x + A[k].y * A[k].y;
            p += (k & 16) ? -m : m;   // k bit 4 = wire-0 bit
        }
        // reduce across lanes sharing the same s2 (lane bits 2..4)
        p += __shfl_xor_sync(0xffffffffu, p, 16);
        p += __shfl_xor_sync(0xffffffffu, p, 8);
        p += __shfl_xor_sync(0xffffffffu, p, 4);
        if ((t & 31) < 4) atomicAdd(out + sBase + (t & 3), p);
    } else {
#pragma unroll
        for (int k = 0; k < 32; k++) {
            int c = (k & 3) | (u << 2) | ((k >> 2) << 8);
            sm[(c << 2) | s2] = A[k];
        }
        __syncthreads();
#pragma unroll
        for (int it = 0; it < 32; it++) {
            int e = t + it * 256;
            int c = e >> 2, ss = e & 3;
            int gi = ((c >> 10) << 19) | (r << 10) | (c & 1023);
            g_state[(gi << 6) + sBase + ss] = sm[e];
        }
    }
}

// ---------------------------------------------------------------------------
extern "C" void kernel_launch(void* const* d_in, const int* in_sizes, int n_in,
                              void* d_out, int out_size) {
    const float* x      = (const float*)d_in[0];
    const float* params = (const float*)d_in[1];
    if (n_in >= 2 && in_sizes[0] == 240 && in_sizes[1] == 1280) {  // defensive swap
        const float* tmp = x; x = params; params = tmp;
    }
    float* out = (float*)d_out;

    const size_t SH = 8192 * sizeof(float2);   // 64 KB dynamic smem
    cudaFuncSetAttribute(pass1_kernel<true>,  cudaFuncAttributeMaxDynamicSharedMemorySize, (int)SH);
    cudaFuncSetAttribute(pass1_kernel<false>, cudaFuncAttributeMaxDynamicSharedMemorySize, (int)SH);
    cudaFuncSetAttribute(pass2_kernel<false>, cudaFuncAttributeMaxDynamicSharedMemorySize, (int)SH);
    cudaFuncSetAttribute(pass2_kernel<true>,  cudaFuncAttributeMaxDynamicSharedMemorySize, (int)SH);

    setup_kernel<<<6, 256>>>(x, params);

    const int GRID = 8192, TB = 256;
    // Layer 0: generate post-RX product state + layer-0 gates
    pass1_kernel<true><<<GRID, TB, SH>>>(0);
    pass2_kernel<false><<<GRID, TB, SH>>>(0, nullptr);
    // Layers 1..2
    for (int d = 1; d <= 2; d++) {
        pass1_kernel<false><<<GRID, TB, SH>>>(d);
        pass2_kernel<false><<<GRID, TB, SH>>>(d, nullptr);
    }
    // Layer 3: last pass folds the <Z_0> reduction
    pass1_kernel<false><<<GRID, TB, SH>>>(3);
    cudaMemsetAsync(d_out, 0, (size_t)out_size * sizeof(float));
    pass2_kernel<true><<<GRID, TB, SH>>>(3, out);
}

// round 4
// speedup vs baseline: 1.7101x; 1.7101x over previous
#include <cuda_runtime.h>
#include <cstdint>

// ============================================================================
// 20-qubit depth-4 strongly-entangling circuit, batch 64, <Z_0>.
// 8 in-place full-state sweeps; each pass has only 10 LOCAL bits:
//   pass1: local c = i bits 10..19 (wires 0..9),  i = (c<<10)|r
//   pass2: local c = i bits 0..9  (wires 10..19), i = (r<<10)|c
// Boundary CNOT(19,0) -> folded into next pass1's load addressing (XOR).
// Boundary CNOT(9,10) -> uniform register-half swap inside pass2 round A.
// c bit j <-> wire (9-j) in pass1, wire (19-j) in pass2.  rm[j] = rot for c bit j.
//
// CTA: 1024 configs x 8 samples (64KB smem), 512 threads, 8 configs x 2
// packed samples per thread (f32x2).  5 register rounds (3 k-bits each):
//   window P=7: rots c9,c8,c7; CNOT(c9,c8),(c8,c7)
//   window P=5: rots c6,c5;    CNOT(c7,c6),(c6,c5)
//   window P=3: rots c4,c3;    CNOT(c5,c4),(c4,c3)
//   window P=1: rots c2,c1;    CNOT(c3,c2),(c2,c1)
//   window P=0: rot  c0;       CNOT(c1,c0)
// Round A loads straight from global (or generates the post-RX product state),
// round E stores straight to global (or reduces <Z_0>).
// ============================================================================

using u64 = unsigned long long;

#define NSTATE (1 << 20)
#define SGN 0x8000000080000000ULL

__device__ float2 g_state[(size_t)NSTATE * 64];      // 512 MB, addr = i*64 + s
__device__ float4 g_rotmP[4 * 2 * 10 * 2];           // [layer][pass][cbit j][2xfloat4]
__device__ float2 g_cs[64 * 20];                     // (cos(x/2), sin(x/2)) per (s,w)

// ---------------- packed f32x2 helpers ----------------
__device__ __forceinline__ u64 f2mul(u64 a, u64 b) {
    u64 d; asm("mul.rn.f32x2 %0,%1,%2;" : "=l"(d) : "l"(a), "l"(b)); return d;
}
__device__ __forceinline__ u64 f2fma(u64 a, u64 b, u64 c) {
    u64 d; asm("fma.rn.f32x2 %0,%1,%2,%3;" : "=l"(d) : "l"(a), "l"(b), "l"(c)); return d;
}
__device__ __forceinline__ u64 f2add(u64 a, u64 b) {
    u64 d; asm("add.rn.f32x2 %0,%1,%2;" : "=l"(d) : "l"(a), "l"(b)); return d;
}
__device__ __forceinline__ u64 f2sub(u64 a, u64 b) {
    u64 d; asm("sub.rn.f32x2 %0,%1,%2;" : "=l"(d) : "l"(a), "l"(b)); return d;
}
__device__ __forceinline__ u64 pk(float lo, float hi) {
    u64 d; asm("mov.b64 %0, {%1, %2};" : "=l"(d) : "f"(lo), "f"(hi)); return d;
}
__device__ __forceinline__ u64 bc(float v) {
    u64 d; asm("mov.b64 %0, {%1, %1};" : "=l"(d) : "f"(v)); return d;
}
__device__ __forceinline__ float2 up(u64 a) {
    float2 r; asm("mov.b64 {%0, %1}, %2;" : "=f"(r.x), "=f"(r.y) : "l"(a)); return r;
}

// ---------------- gate primitives on 8-config register block ----------------
// m[8] = packed-broadcast {m00x,m00y,m01x,m01y,m10x,m10y,m11x,m11y}
template <int Q>
__device__ __forceinline__ void rotP(u64* X, u64* Y, const u64* m) {
#pragma unroll
    for (int k = 0; k < 8; k++) {
        if (k & (1 << Q)) continue;
        const int k1 = k | (1 << Q);
        const u64 aX = X[k], aY = Y[k], bX = X[k1], bY = Y[k1];
        const u64 aYn = aY ^ SGN, bYn = bY ^ SGN;
        X[k]  = f2fma(m[3], bYn, f2fma(m[2], bX, f2fma(m[1], aYn, f2mul(m[0], aX))));
        Y[k]  = f2fma(m[3], bX,  f2fma(m[2], bY, f2fma(m[1], aX,  f2mul(m[0], aY))));
        X[k1] = f2fma(m[7], bYn, f2fma(m[6], bX, f2fma(m[5], aYn, f2mul(m[4], aX))));
        Y[k1] = f2fma(m[7], bX,  f2fma(m[6], bY, f2fma(m[5], aX,  f2mul(m[4], aY))));
    }
}

template <int QC, int QT>
__device__ __forceinline__ void cnotP(u64* X, u64* Y) {
#pragma unroll
    for (int k = 0; k < 8; k++) {
        if ((k & (1 << QC)) && !(k & (1 << QT))) {
            const int k1 = k | (1 << QT);
            u64 t = X[k]; X[k] = X[k1]; X[k1] = t;
            t = Y[k]; Y[k] = Y[k1]; Y[k1] = t;
        }
    }
}

__device__ __forceinline__ void ldm(const float4* rmG, int j, u64* m) {
    const float4 a = rmG[j * 2], b = rmG[j * 2 + 1];
    m[0] = bc(a.x); m[1] = bc(a.y); m[2] = bc(a.z); m[3] = bc(a.w);
    m[4] = bc(b.x); m[5] = bc(b.y); m[6] = bc(b.z); m[7] = bc(b.w);
}

// ---------------- smem round-crossing ----------------
template <int P>
__device__ __forceinline__ int cfg(int u, int k) {
    return ((u >> P) << (P + 3)) | (k << P) | (u & ((1 << P) - 1));
}
__device__ __forceinline__ int swz(int idx) { return idx ^ (((idx >> 5) & 3) << 2); }

template <int P>
__device__ __forceinline__ void stR(u64* smX, u64* smY, int u, int s2, const u64* X, const u64* Y) {
#pragma unroll
    for (int k = 0; k < 8; k++) {
        const int idx = swz((cfg<P>(u, k) << 2) | s2);
        smX[idx] = X[k]; smY[idx] = Y[k];
    }
}
template <int P>
__device__ __forceinline__ void ldR(const u64* smX, const u64* smY, int u, int s2, u64* X, u64* Y) {
#pragma unroll
    for (int k = 0; k < 8; k++) {
        const int idx = swz((cfg<P>(u, k) << 2) | s2);
        X[k] = smX[idx]; Y[k] = smY[idx];
    }
}

// ---------------- setup ----------------
__global__ void setup_kernel(const float* __restrict__ x,
                             const float* __restrict__ params) {
    int t = blockIdx.x * blockDim.x + threadIdx.x;
    if (t < 80) {
        // t = layer*20 + pass*10 + j ; wire = pass ? 19-j : 9-j
        int layer = t / 20, rest = t % 20, pass = rest / 10, j = rest % 10;
        int wire = pass ? (19 - j) : (9 - j);
        float phi = params[(layer * 20 + wire) * 3 + 0];
        float th  = params[(layer * 20 + wire) * 3 + 1];
        float om  = params[(layer * 20 + wire) * 3 + 2];
        float ct, st;  sincosf(0.5f * th, &st, &ct);
        float ap = -0.5f * (phi + om);
        float am =  0.5f * (phi - om);
        float ca, sa;  sincosf(ap, &sa, &ca);
        float cb, sb;  sincosf(am, &sb, &cb);
        // m00 = e^{i ap} ct ; m01 = -e^{i am} st ; m10 = e^{-i am} st ; m11 = conj(m00)
        g_rotmP[t * 2 + 0] = make_float4( ca * ct,  sa * ct, -cb * st, -sb * st);
        g_rotmP[t * 2 + 1] = make_float4( cb * st, -sb * st,  ca * ct, -sa * ct);
    }
    int v = t - 80;
    if (v >= 0 && v < 64 * 20) {
        float c, s;  sincosf(0.5f * x[v], &s, &c);
        g_cs[v] = make_float2(c, s);
    }
}

__device__ __forceinline__ float2 rxf(float2 v, float2 f, int bit) {
    if (bit) return make_float2(f.y * v.y, -f.y * v.x);
    return make_float2(f.x * v.x, f.x * v.y);
}

// ---------------- main pass kernel ----------------
// PASS: 0 = pass1, 1 = pass2.  MODE: 0 normal, 1 GEN (layer0 pass1), 2 RED.
template <int PASS, int MODE>
__global__ void __launch_bounds__(512, 2) qpass(int layer, float* out) {
    extern __shared__ u64 sm[];
    u64* smX = sm;
    u64* smY = sm + 4096;
    const int t  = threadIdx.x;
    const int s2 = t & 3;            // sample-pair id (2 samples each)
    const int u  = t >> 2;           // 7 bits: complement of round's 3 k-bits
    const int r  = blockIdx.x & 1023;
    const int sg = blockIdx.x >> 10;
    const int sOff = sg * 4 + s2;    // float4 index within 32 float4s per i
    float4* g4 = (float4*)g_state;
    const float4* rmG = g_rotmP + (layer * 2 + PASS) * 20;

    u64 X[8], Y[8];
    u64 m[8];

    // ================= Round A (window P=7: k0=c7,k1=c8,k2=c9) =================
    if (MODE == 1) {
        // Generate post-RX product state directly in round-A order.
        const float2* csA = g_cs + (sg * 8 + s2 * 2) * 20;
        const float2* csB = csA + 20;
        float2 a0 = make_float2(1.f, 0.f), a1 = make_float2(1.f, 0.f);
#pragma unroll
        for (int p = 0; p < 10; p++) {      // i bits 0..9 (= r), wire 19-p
            const int b = (r >> p) & 1;
            a0 = rxf(a0, csA[19 - p], b);
            a1 = rxf(a1, csB[19 - p], b);
        }
#pragma unroll
        for (int j = 0; j < 7; j++) {       // c bits 0..6 (= u), wire 9-j
            const int b = (u >> j) & 1;
            a0 = rxf(a0, csA[9 - j], b);
            a1 = rxf(a1, csB[9 - j], b);
        }
#pragma unroll
        for (int k = 0; k < 8; k++) {       // k0->wire2, k1->wire1, k2->wire0
            float2 w0 = a0, w1 = a1;
            w0 = rxf(w0, csA[2], k & 1);        w1 = rxf(w1, csB[2], k & 1);
            w0 = rxf(w0, csA[1], (k >> 1) & 1); w1 = rxf(w1, csB[1], (k >> 1) & 1);
            w0 = rxf(w0, csA[0], (k >> 2) & 1); w1 = rxf(w1, csB[0], (k >> 2) & 1);
            X[k] = pk(w0.x, w1.x);
            Y[k] = pk(w0.y, w1.y);
        }
    } else {
        // pass1 (layer>=1): incoming CNOT(19,0) -> read src c XOR ((r&1)<<9)
        const int cx = (PASS == 0 && layer > 0) ? ((r & 1) << 9) : 0;
#pragma unroll
        for (int k = 0; k < 8; k++) {
            const int c = ((k << 7) | u) ^ cx;
            const int i = (PASS == 0) ? ((c << 10) | r) : ((r << 10) | c);
            const float4 v = g4[(i << 5) + sOff];
            X[k] = pk(v.x, v.z);
            Y[k] = pk(v.y, v.w);
        }
    }
    ldm(rmG, 9, m); rotP<2>(X, Y, m);       // rot c9
    ldm(rmG, 8, m); rotP<1>(X, Y, m);       // rot c8
    ldm(rmG, 7, m); rotP<0>(X, Y, m);       // rot c7
    if (PASS == 1 && (r & 1)) {             // CNOT(9,10): uniform flip of c9
#pragma unroll
        for (int k = 0; k < 4; k++) {
            u64 t0 = X[k]; X[k] = X[k + 4]; X[k + 4] = t0;
            t0 = Y[k]; Y[k] = Y[k + 4]; Y[k + 4] = t0;
        }
    }
    cnotP<2, 1>(X, Y);                      // CNOT(c9,c8)
    cnotP<1, 0>(X, Y);                      // CNOT(c8,c7)
    stR<7>(smX, smY, u, s2, X, Y);
    __syncthreads();

    // ================= Round B (P=5: k0=c5,k1=c6,k2=c7) =================
    ldR<5>(smX, smY, u, s2, X, Y);
    ldm(rmG, 6, m); rotP<1>(X, Y, m);       // rot c6
    ldm(rmG, 5, m); rotP<0>(X, Y, m);       // rot c5
    cnotP<2, 1>(X, Y);                      // CNOT(c7,c6)
    cnotP<1, 0>(X, Y);                      // CNOT(c6,c5)
    __syncthreads();
    stR<5>(smX, smY, u, s2, X, Y);
    __syncthreads();

    // ================= Round C (P=3: k0=c3,k1=c4,k2=c5) =================
    ldR<3>(smX, smY, u, s2, X, Y);
    ldm(rmG, 4, m); rotP<1>(X, Y, m);       // rot c4
    ldm(rmG, 3, m); rotP<0>(X, Y, m);       // rot c3
    cnotP<2, 1>(X, Y);                      // CNOT(c5,c4)
    cnotP<1, 0>(X, Y);                      // CNOT(c4,c3)
    __syncthreads();
    stR<3>(smX, smY, u, s2, X, Y);
    __syncthreads();

    // ================= Round D (P=1: k0=c1,k1=c2,k2=c3) =================
    ldR<1>(smX, smY, u, s2, X, Y);
    ldm(rmG, 2, m); rotP<1>(X, Y, m);       // rot c2
    ldm(rmG, 1, m); rotP<0>(X, Y, m);       // rot c1
    cnotP<2, 1>(X, Y);                      // CNOT(c3,c2)
    cnotP<1, 0>(X, Y);                      // CNOT(c2,c1)
    __syncthreads();
    stR<1>(smX, smY, u, s2, X, Y);
    __syncthreads();

    // ================= Round E (P=0: k0=c0,k1=c1,k2=c2) =================
    ldR<0>(smX, smY, u, s2, X, Y);
    ldm(rmG, 0, m); rotP<0>(X, Y, m);       // rot c0
    cnotP<1, 0>(X, Y);                      // CNOT(c1,c0)

    if (MODE == 2) {
        // <Z_0> with the final CNOT(19,0) folded: sign = bit19(i) ^ bit0(i)
        // pass2: bit19 = r>>9, bit0 = c bit0 = k0.
        u64 ps = 0;
        const int sb = (r >> 9) & 1;
#pragma unroll
        for (int k = 0; k < 8; k++) {
            const u64 mag = f2fma(Y[k], Y[k], f2mul(X[k], X[k]));
            if (((k ^ sb) & 1) == 0) ps = f2add(ps, mag);
            else                     ps = f2sub(ps, mag);
        }
        ps = f2add(ps, __shfl_xor_sync(0xffffffffu, ps, 4));
        ps = f2add(ps, __shfl_xor_sync(0xffffffffu, ps, 8));
        ps = f2add(ps, __shfl_xor_sync(0xffffffffu, ps, 16));
        __syncthreads();                    // smem reuse barrier
        const int lane = t & 31, wid = t >> 5;
        if (lane < 4) smX[wid * 4 + lane] = ps;
        __syncthreads();
        if (t < 4) {
            float2 acc = make_float2(0.f, 0.f);
#pragma unroll
            for (int w = 0; w < 16; w++) {
                const float2 q = up(smX[w * 4 + t]);
                acc.x += q.x; acc.y += q.y;
            }
            atomicAdd(out + sg * 8 + t * 2 + 0, acc.x);
            atomicAdd(out + sg * 8 + t * 2 + 1, acc.y);
        }
    } else {
#pragma unroll
        for (int k = 0; k < 8; k++) {
            const int c = (u << 3) | k;
            const int i = (PASS == 0) ? ((c << 10) | r) : ((r << 10) | c);
            const float2 xx = up(X[k]);
            const float2 yy = up(Y[k]);
            g4[(i << 5) + sOff] = make_float4(xx.x, yy.x, xx.y, yy.y);
        }
    }
}

// ---------------------------------------------------------------------------
extern "C" void kernel_launch(void* const* d_in, const int* in_sizes, int n_in,
                              void* d_out, int out_size) {
    const float* x      = (const float*)d_in[0];
    const float* params = (const float*)d_in[1];
    if (n_in >= 2 && in_sizes[0] == 240 && in_sizes[1] == 1280) {  // defensive swap
        const float* tmp = x; x = params; params = tmp;
    }
    float* out = (float*)d_out;

    const size_t SH = 8192 * sizeof(u64);   // 64 KB dynamic smem
    cudaFuncSetAttribute(qpass<0, 1>, cudaFuncAttributeMaxDynamicSharedMemorySize, (int)SH);
    cudaFuncSetAttribute(qpass<0, 0>, cudaFuncAttributeMaxDynamicSharedMemorySize, (int)SH);
    cudaFuncSetAttribute(qpass<1, 0>, cudaFuncAttributeMaxDynamicSharedMemorySize, (int)SH);
    cudaFuncSetAttribute(qpass<1, 2>, cudaFuncAttributeMaxDynamicSharedMemorySize, (int)SH);

    setup_kernel<<<6, 256>>>(x, params);

    const int GRID = 8192, TB = 512;
    qpass<0, 1><<<GRID, TB, SH>>>(0, nullptr);   // layer0 pass1: GEN
    qpass<1, 0><<<GRID, TB, SH>>>(0, nullptr);
    for (int d = 1; d <= 2; d++) {
        qpass<0, 0><<<GRID, TB, SH>>>(d, nullptr);
        qpass<1, 0><<<GRID, TB, SH>>>(d, nullptr);
    }
    qpass<0, 0><<<GRID, TB, SH>>>(3, nullptr);
    cudaMemsetAsync(d_out, 0, (size_t)out_size * sizeof(float));
    qpass<1, 2><<<GRID, TB, SH>>>(3, out);       // layer3 pass2: RED
}

// round 5
// speedup vs baseline: 1.9787x; 1.1571x over previous
#include <cuda_runtime.h>
#include <cstdint>

// ============================================================================
// 20-qubit depth-4 strongly-entangling circuit, batch 64, <Z_0>.
// 8 in-place full-state sweeps; each pass has 10 LOCAL bits:
//   pass1: local c = i bits 10..19 (wires 0..9),  i = (c<<10)|r
//   pass2: local c = i bits 0..9  (wires 10..19), i = (r<<10)|c
// Boundary CNOT(19,0) -> folded into next pass1's load addressing (k3 XOR).
// Boundary CNOT(9,10) -> uniform register half-swap inside pass2 window 1.
// c bit j <-> wire (9-j) in pass1, wire (19-j) in pass2.  rm[j] = rot for c bit j.
//
// CTA: 1024 configs x 8 samples (64KB smem), 256 threads, 16 configs x 2
// packed samples per thread (f32x2).  THREE register windows of 4 k-bits:
//   W1 k=c{6..9}: rots c9,c8,c7,c6 ; CNOT(c9,c8)(c8,c7)(c7,c6)
//   W2 k=c{3..6}: rots c5,c4,c3    ; CNOT(c6,c5)(c5,c4)(c4,c3)
//   W3 k=c{0..3}: rots c2,c1,c0    ; CNOT(c3,c2)(c2,c1)(c1,c0)
// W1 loads straight from global (or generates the post-RX product state),
// W3 stores straight to global (or reduces <Z_0>).  Only 2 __syncthreads:
// intra-window smem ld/st address sets are thread-identical (no barrier needed).
// ============================================================================

using u64 = unsigned long long;

#define NSTATE (1 << 20)
#define SGN 0x8000000080000000ULL

__device__ float2 g_state[(size_t)NSTATE * 64];      // 512 MB, addr = i*64 + s
__device__ float4 g_rotmP[4 * 2 * 10 * 2];           // [layer][pass][cbit j][2xfloat4]
__device__ float2 g_cs[64 * 20];                     // (cos(x/2), sin(x/2)) per (s,w)

// ---------------- packed f32x2 helpers ----------------
__device__ __forceinline__ u64 f2mul(u64 a, u64 b) {
    u64 d; asm("mul.rn.f32x2 %0,%1,%2;" : "=l"(d) : "l"(a), "l"(b)); return d;
}
__device__ __forceinline__ u64 f2fma(u64 a, u64 b, u64 c) {
    u64 d; asm("fma.rn.f32x2 %0,%1,%2,%3;" : "=l"(d) : "l"(a), "l"(b), "l"(c)); return d;
}
__device__ __forceinline__ u64 f2add(u64 a, u64 b) {
    u64 d; asm("add.rn.f32x2 %0,%1,%2;" : "=l"(d) : "l"(a), "l"(b)); return d;
}
__device__ __forceinline__ u64 f2sub(u64 a, u64 b) {
    u64 d; asm("sub.rn.f32x2 %0,%1,%2;" : "=l"(d) : "l"(a), "l"(b)); return d;
}
__device__ __forceinline__ u64 pk(float lo, float hi) {
    u64 d; asm("mov.b64 %0, {%1, %2};" : "=l"(d) : "f"(lo), "f"(hi)); return d;
}
__device__ __forceinline__ u64 bc(float v) {
    u64 d; asm("mov.b64 %0, {%1, %1};" : "=l"(d) : "f"(v)); return d;
}
__device__ __forceinline__ float2 up(u64 a) {
    float2 r; asm("mov.b64 {%0, %1}, %2;" : "=f"(r.x), "=f"(r.y) : "l"(a)); return r;
}

// ---------------- gate primitives on 16-config register block ----------------
// m[8] = packed-broadcast {m00x,m00y,m01x,m01y,m10x,m10y,m11x,m11y}
template <int Q>
__device__ __forceinline__ void rotg(u64* X, u64* Y, const u64* m) {
#pragma unroll
    for (int k = 0; k < 16; k++) {
        if (k & (1 << Q)) continue;
        const int k1 = k | (1 << Q);
        const u64 aX = X[k], aY = Y[k], bX = X[k1], bY = Y[k1];
        const u64 aYn = aY ^ SGN, bYn = bY ^ SGN;
        X[k]  = f2fma(m[3], bYn, f2fma(m[2], bX, f2fma(m[1], aYn, f2mul(m[0], aX))));
        Y[k]  = f2fma(m[3], bX,  f2fma(m[2], bY, f2fma(m[1], aX,  f2mul(m[0], aY))));
        X[k1] = f2fma(m[7], bYn, f2fma(m[6], bX, f2fma(m[5], aYn, f2mul(m[4], aX))));
        Y[k1] = f2fma(m[7], bX,  f2fma(m[6], bY, f2fma(m[5], aX,  f2mul(m[4], aY))));
    }
}

template <int QC, int QT>
__device__ __forceinline__ void cnotg(u64* X, u64* Y) {
#pragma unroll
    for (int k = 0; k < 16; k++) {
        if ((k & (1 << QC)) && !(k & (1 << QT))) {
            const int k1 = k | (1 << QT);
            u64 t = X[k]; X[k] = X[k1]; X[k1] = t;
            t = Y[k]; Y[k] = Y[k1]; Y[k1] = t;
        }
    }
}

__device__ __forceinline__ void ldm(const float4* rmG, int j, u64* m) {
    const float4 a = rmG[j * 2], b = rmG[j * 2 + 1];
    m[0] = bc(a.x); m[1] = bc(a.y); m[2] = bc(a.z); m[3] = bc(a.w);
    m[4] = bc(b.x); m[5] = bc(b.y); m[6] = bc(b.z); m[7] = bc(b.w);
}

// ---------------- smem round-crossing (16B elements) ----------------
template <int P>
__device__ __forceinline__ int cfg(int u, int k) {
    return ((u >> P) << (P + 4)) | (k << P) | (u & ((1 << P) - 1));
}
__device__ __forceinline__ int swz(int idx) { return idx ^ (((idx >> 6) & 1) << 2); }

template <int P>
__device__ __forceinline__ void stR(ulonglong2* sm2, int u, int s2, const u64* X, const u64* Y) {
#pragma unroll
    for (int k = 0; k < 16; k++) {
        const int idx = swz((cfg<P>(u, k) << 2) | s2);
        ulonglong2 v; v.x = X[k]; v.y = Y[k];
        sm2[idx] = v;
    }
}
template <int P>
__device__ __forceinline__ void ldR(const ulonglong2* sm2, int u, int s2, u64* X, u64* Y) {
#pragma unroll
    for (int k = 0; k < 16; k++) {
        const int idx = swz((cfg<P>(u, k) << 2) | s2);
        const ulonglong2 v = sm2[idx];
        X[k] = v.x; Y[k] = v.y;
    }
}

// ---------------- setup ----------------
__global__ void setup_kernel(const float* __restrict__ x,
                             const float* __restrict__ params) {
    int t = blockIdx.x * blockDim.x + threadIdx.x;
    if (t < 80) {
        // t = layer*20 + pass*10 + j ; wire = pass ? 19-j : 9-j
        int layer = t / 20, rest = t % 20, pass = rest / 10, j = rest % 10;
        int wire = pass ? (19 - j) : (9 - j);
        float phi = params[(layer * 20 + wire) * 3 + 0];
        float th  = params[(layer * 20 + wire) * 3 + 1];
        float om  = params[(layer * 20 + wire) * 3 + 2];
        float ct, st;  sincosf(0.5f * th, &st, &ct);
        float ap = -0.5f * (phi + om);
        float am =  0.5f * (phi - om);
        float ca, sa;  sincosf(ap, &sa, &ca);
        float cb, sb;  sincosf(am, &sb, &cb);
        // m00 = e^{i ap} ct ; m01 = -e^{i am} st ; m10 = e^{-i am} st ; m11 = conj(m00)
        g_rotmP[t * 2 + 0] = make_float4( ca * ct,  sa * ct, -cb * st, -sb * st);
        g_rotmP[t * 2 + 1] = make_float4( cb * st, -sb * st,  ca * ct, -sa * ct);
    }
    int v = t - 80;
    if (v >= 0 && v < 64 * 20) {
        float c, s;  sincosf(0.5f * x[v], &s, &c);
        g_cs[v] = make_float2(c, s);
    }
}

__device__ __forceinline__ float2 rxf(float2 v, float2 f, int bit) {
    if (bit) return make_float2(f.y * v.y, -f.y * v.x);
    return make_float2(f.x * v.x, f.x * v.y);
}

// ---------------- main pass kernel ----------------
// PASS: 0 = pass1, 1 = pass2.  MODE: 0 normal, 1 GEN (layer0 pass1), 2 RED.
template <int PASS, int MODE>
__global__ void __launch_bounds__(256, 2) qpass(int layer, float* __restrict__ out) {
    extern __shared__ ulonglong2 sm2[];          // 4096 x 16B = 64KB
    const int t  = threadIdx.x;
    const int s2 = t & 3;            // sample-pair id (2 samples each)
    const int u  = t >> 2;           // 6 bits: complement of window's 4 k-bits
    const int r  = blockIdx.x & 1023;
    const int sg = blockIdx.x >> 10;
    const int sOff = sg * 4 + s2;    // float4 index within 32 float4s per i
    float4* g4 = (float4*)g_state;
    const float4* rmG = g_rotmP + (layer * 2 + PASS) * 20;

    u64 X[16], Y[16];
    u64 m[8];

    // ================= Window 1 (k_q <-> c_{6+q}) =================
    if (MODE == 1) {
        // Generate post-RX product state directly (layer0 pass1).
        const float2* csA = g_cs + (sg * 8 + s2 * 2) * 20;
        const float2* csB = csA + 20;
        float2 a0 = make_float2(1.f, 0.f), a1 = make_float2(1.f, 0.f);
#pragma unroll
        for (int p = 0; p < 10; p++) {      // i bits 0..9 (= r), wire 19-p
            const int b = (r >> p) & 1;
            a0 = rxf(a0, csA[19 - p], b);
            a1 = rxf(a1, csB[19 - p], b);
        }
#pragma unroll
        for (int j = 0; j < 6; j++) {       // c bits 0..5 (= u), wire 9-j
            const int b = (u >> j) & 1;
            a0 = rxf(a0, csA[9 - j], b);
            a1 = rxf(a1, csB[9 - j], b);
        }
#pragma unroll
        for (int k = 0; k < 16; k++) {      // k_q -> wire 3-q
            float2 w0 = a0, w1 = a1;
#pragma unroll
            for (int q = 0; q < 4; q++) {
                const int b = (k >> q) & 1;
                w0 = rxf(w0, csA[3 - q], b);
                w1 = rxf(w1, csB[3 - q], b);
            }
            X[k] = pk(w0.x, w1.x);
            Y[k] = pk(w0.y, w1.y);
        }
    } else {
        // pass1 (layer>=1): incoming CNOT(19,0) -> flip k3 of the source index
        const int kx = (PASS == 0 && layer > 0) ? ((r & 1) << 3) : 0;
#pragma unroll
        for (int k = 0; k < 16; k++) {
            const int c = ((k ^ kx) << 6) | u;
            const int i = (PASS == 0) ? ((c << 10) | r) : ((r << 10) | c);
            const float4 v = g4[((size_t)i << 5) + sOff];
            X[k] = pk(v.x, v.z);
            Y[k] = pk(v.y, v.w);
        }
    }
    ldm(rmG, 9, m); rotg<3>(X, Y, m);       // rot c9
    ldm(rmG, 8, m); rotg<2>(X, Y, m);       // rot c8
    ldm(rmG, 7, m); rotg<1>(X, Y, m);       // rot c7
    ldm(rmG, 6, m); rotg<0>(X, Y, m);       // rot c6
    if (PASS == 1 && (r & 1)) {             // CNOT(9,10): uniform flip of c9 (k3)
#pragma unroll
        for (int k = 0; k < 8; k++) {
            u64 t0 = X[k]; X[k] = X[k + 8]; X[k + 8] = t0;
            t0 = Y[k]; Y[k] = Y[k + 8]; Y[k + 8] = t0;
        }
    }
    cnotg<3, 2>(X, Y);                      // CNOT(c9,c8)
    cnotg<2, 1>(X, Y);                      // CNOT(c8,c7)
    cnotg<1, 0>(X, Y);                      // CNOT(c7,c6)
    stR<6>(sm2, u, s2, X, Y);
    __syncthreads();

    // ================= Window 2 (k_q <-> c_{3+q}) =================
    ldR<3>(sm2, u, s2, X, Y);
    ldm(rmG, 5, m); rotg<2>(X, Y, m);       // rot c5
    ldm(rmG, 4, m); rotg<1>(X, Y, m);       // rot c4
    ldm(rmG, 3, m); rotg<0>(X, Y, m);       // rot c3
    cnotg<3, 2>(X, Y);                      // CNOT(c6,c5)
    cnotg<2, 1>(X, Y);                      // CNOT(c5,c4)
    cnotg<1, 0>(X, Y);                      // CNOT(c4,c3)
    stR<3>(sm2, u, s2, X, Y);               // same per-thread addresses as ldR<3>
    __syncthreads();

    // ================= Window 3 (k_q <-> c_q) =================
    ldR<0>(sm2, u, s2, X, Y);
    ldm(rmG, 2, m); rotg<2>(X, Y, m);       // rot c2
    ldm(rmG, 1, m); rotg<1>(X, Y, m);       // rot c1
    ldm(rmG, 0, m); rotg<0>(X, Y, m);       // rot c0
    cnotg<3, 2>(X, Y);                      // CNOT(c3,c2)
    cnotg<2, 1>(X, Y);                      // CNOT(c2,c1)
    cnotg<1, 0>(X, Y);                      // CNOT(c1,c0)

    if (MODE == 2) {
        // <Z_0> with final CNOT(19,0) folded: sign = bit19(i) ^ bit0(i)
        // pass2: bit19 = r bit 9, bit0 = c bit 0 = k0.
        u64 ps = 0;
        const int sb = (r >> 9) & 1;
#pragma unroll
        for (int k = 0; k < 16; k++) {
            const u64 mag = f2fma(Y[k], Y[k], f2mul(X[k], X[k]));
            if (((k ^ sb) & 1) == 0) ps = f2add(ps, mag);
            else                     ps = f2sub(ps, mag);
        }
        ps = f2add(ps, __shfl_xor_sync(0xffffffffu, ps, 4));
        ps = f2add(ps, __shfl_xor_sync(0xffffffffu, ps, 8));
        ps = f2add(ps, __shfl_xor_sync(0xffffffffu, ps, 16));
        __syncthreads();                    // smem reuse barrier
        u64* smr = (u64*)sm2;
        const int lane = t & 31, wid = t >> 5;
        if (lane < 4) smr[wid * 4 + lane] = ps;
        __syncthreads();
        if (t < 4) {
            float2 acc = make_float2(0.f, 0.f);
#pragma unroll
            for (int w = 0; w < 8; w++) {
                const float2 q = up(smr[w * 4 + t]);
                acc.x += q.x; acc.y += q.y;
            }
            atomicAdd(out + sg * 8 + t * 2 + 0, acc.x);
            atomicAdd(out + sg * 8 + t * 2 + 1, acc.y);
        }
    } else {
#pragma unroll
        for (int k = 0; k < 16; k++) {
            const int c = (u << 4) | k;
            const int i = (PASS == 0) ? ((c << 10) | r) : ((r << 10) | c);
            const float2 xx = up(X[k]);
            const float2 yy = up(Y[k]);
            g4[((size_t)i << 5) + sOff] = make_float4(xx.x, yy.x, xx.y, yy.y);
        }
    }
}

// ---------------------------------------------------------------------------
extern "C" void kernel_launch(void* const* d_in, const int* in_sizes, int n_in,
                              void* d_out, int out_size) {
    const float* x      = (const float*)d_in[0];
    const float* params = (const float*)d_in[1];
    if (n_in >= 2 && in_sizes[0] == 240 && in_sizes[1] == 1280) {  // defensive swap
        const float* tmp = x; x = params; params = tmp;
    }
    float* out = (float*)d_out;

    const size_t SH = 4096 * sizeof(ulonglong2);   // 64 KB dynamic smem
    cudaFuncSetAttribute(qpass<0, 1>, cudaFuncAttributeMaxDynamicSharedMemorySize, (int)SH);
    cudaFuncSetAttribute(qpass<0, 0>, cudaFuncAttributeMaxDynamicSharedMemorySize, (int)SH);
    cudaFuncSetAttribute(qpass<1, 0>, cudaFuncAttributeMaxDynamicSharedMemorySize, (int)SH);
    cudaFuncSetAttribute(qpass<1, 2>, cudaFuncAttributeMaxDynamicSharedMemorySize, (int)SH);

    setup_kernel<<<6, 256>>>(x, params);

    const int GRID = 8192, TB = 256;
    qpass<0, 1><<<GRID, TB, SH>>>(0, nullptr);   // layer0 pass1: GEN
    qpass<1, 0><<<GRID, TB, SH>>>(0, nullptr);
    for (int d = 1; d <= 2; d++) {
        qpass<0, 0><<<GRID, TB, SH>>>(d, nullptr);
        qpass<1, 0><<<GRID, TB, SH>>>(d, nullptr);
    }
    qpass<0, 0><<<GRID, TB, SH>>>(3, nullptr);
    cudaMemsetAsync(d_out, 0, (size_t)out_size * sizeof(float));
    qpass<1, 2><<<GRID, TB, SH>>>(3, out);       // layer3 pass2: RED
}

// round 7
// speedup vs baseline: 2.2846x; 1.1546x over previous
#include <cuda_runtime.h>
#include <cstdint>

// ============================================================================
// 20-qubit depth-4 strongly-entangling circuit, batch 64, <Z_0>.
// 8 full-state sweeps, ping-pong between two 512MB buffers whose layouts are
// chosen so every pass READS a contiguous 64KB block per CTA:
//   buffer A (input of pass1): float4 idx = r1*32768 + sg*4096 + c1*4 + s2
//        r1 = i bits 0..9, c1 = i bits 10..19 (pass1 local), s = sg*8+s_lo
//   buffer B (input of pass2): float4 idx = r2*32768 + sg*4096 + c2*4 + s2
//        r2 = i bits 10..19, c2 = i bits 0..9 (pass2 local)
// pass1: reads A dense, writes B scattered (64B segs).  pass2: reads B dense,
// writes A scattered.  CNOT(19,0) folded into pass2's write address XOR,
// CNOT(9,10) folded into a uniform store-index mask in pass2 window 1.
// All in-window CNOT chains are linear -> folded statically into store indices
// (permk = prefix parity).  Rot uses m11=conj(m00), m10=-conj(m01): 7
// broadcast scalars, negations precomputed -> zero sign-flip ALU ops.
// Streaming cache hints (__ldcs/__stcs): 512MB working set >> 126MB L2,
// every byte touched once per pass.
//
// CTA: 1024 configs x 8 samples (64KB smem), 256 threads, 16 configs x 2
// packed samples (f32x2) per thread.  Three register windows of 4 k-bits:
//   W1 k=c{6..9}: rots c9,c8,c7,c6 ; CNOTs (c9,c8)(c8,c7)(c7,c6) [folded]
//   W2 k=c{3..6}: rots c5,c4,c3    ; CNOTs (c6,c5)(c5,c4)(c4,c3) [folded]
//   W3 k=c{0..3}: rots c2,c1,c0    ; CNOTs (c3,c2)(c2,c1)(c1,c0) [folded]
// Only 2 __syncthreads per pass.
// ============================================================================

using u64 = unsigned long long;

#define NSTATE (1 << 20)

__device__ float2 g_A[(size_t)NSTATE * 64];          // 512 MB
__device__ float2 g_B[(size_t)NSTATE * 64];          // 512 MB
__device__ ulonglong2 g_rotB[4 * 2 * 10 * 4];        // 7 broadcast u64 + pad per rot
__device__ float2 g_cs[64 * 20];                     // (cos(x/2), sin(x/2)) per (s,w)

// ---------------- packed f32x2 helpers ----------------
__device__ __forceinline__ u64 f2mul(u64 a, u64 b) {
    u64 d; asm("mul.rn.f32x2 %0,%1,%2;" : "=l"(d) : "l"(a), "l"(b)); return d;
}
__device__ __forceinline__ u64 f2fma(u64 a, u64 b, u64 c) {
    u64 d; asm("fma.rn.f32x2 %0,%1,%2,%3;" : "=l"(d) : "l"(a), "l"(b), "l"(c)); return d;
}
__device__ __forceinline__ u64 f2add(u64 a, u64 b) {
    u64 d; asm("add.rn.f32x2 %0,%1,%2;" : "=l"(d) : "l"(a), "l"(b)); return d;
}
__device__ __forceinline__ u64 f2sub(u64 a, u64 b) {
    u64 d; asm("sub.rn.f32x2 %0,%1,%2;" : "=l"(d) : "l"(a), "l"(b)); return d;
}
__device__ __forceinline__ u64 pk(float lo, float hi) {
    u64 d; asm("mov.b64 %0, {%1, %2};" : "=l"(d) : "f"(lo), "f"(hi)); return d;
}
__device__ __forceinline__ float2 up(u64 a) {
    float2 r; asm("mov.b64 {%0, %1}, %2;" : "=f"(r.x), "=f"(r.y) : "l"(a)); return r;
}
__device__ __forceinline__ u64 dupf(float v) {
    unsigned b = __float_as_uint(v); return (u64)b | ((u64)b << 32);
}

// ---------------- static CNOT-chain permutation (prefix parity) ----------------
// chain (k3,k2)(k2,k1)(k1,k0): d3=k3, d2=k2^k3, d1=k1^k2^k3, d0=k0^k1^k2^k3
__device__ __forceinline__ constexpr int permk(int k) {
    int p3 = (k >> 3) & 1;
    int p2 = ((k >> 2) & 1) ^ p3;
    int p1 = ((k >> 1) & 1) ^ p2;
    int p0 = (k & 1) ^ p1;
    return (p3 << 3) | (p2 << 2) | (p1 << 1) | p0;
}

// ---------------- Rot on 16-config register block ----------------
// m: {m00x, m00y, -m00y, m01x, -m01x, m01y, -m01y} broadcast in f32x2 pairs.
template <int Q>
__device__ __forceinline__ void rotg(u64* X, u64* Y, const u64* m) {
#pragma unroll
    for (int k = 0; k < 16; k++) {
        if (k & (1 << Q)) continue;
        const int k1 = k | (1 << Q);
        const u64 aX = X[k], aY = Y[k], bX = X[k1], bY = Y[k1];
        X[k]  = f2fma(m[6], bY, f2fma(m[3], bX, f2fma(m[2], aY, f2mul(m[0], aX))));
        Y[k]  = f2fma(m[5], bX, f2fma(m[3], bY, f2fma(m[1], aX, f2mul(m[0], aY))));
        X[k1] = f2fma(m[1], bY, f2fma(m[0], bX, f2fma(m[6], aY, f2mul(m[4], aX))));
        Y[k1] = f2fma(m[2], bX, f2fma(m[0], bY, f2fma(m[5], aX, f2mul(m[4], aY))));
    }
}

__device__ __forceinline__ void ldm(const ulonglong2* rmB, int j, u64* m) {
    const ulonglong2 q0 = rmB[j * 4 + 0], q1 = rmB[j * 4 + 1];
    const ulonglong2 q2 = rmB[j * 4 + 2], q3 = rmB[j * 4 + 3];
    m[0] = q0.x; m[1] = q0.y; m[2] = q1.x; m[3] = q1.y;
    m[4] = q2.x; m[5] = q2.y; m[6] = q3.x;
}

// ---------------- smem round-crossing (16B elements) ----------------
template <int P>
__device__ __forceinline__ int cfg(int u, int k) {
    return ((u >> P) << (P + 4)) | (k << P) | (u & ((1 << P) - 1));
}
__device__ __forceinline__ int swz(int idx) { return idx ^ (((idx >> 6) & 1) << 2); }

// store with the window's CNOT chain folded into the destination index
template <int P>
__device__ __forceinline__ void stR(ulonglong2* sm2, int u, int s2,
                                    const u64* X, const u64* Y, int xm) {
#pragma unroll
    for (int k = 0; k < 16; k++) {
        const int d = permk(k);
        const int idx = swz((cfg<P>(u, d) << 2) | s2) ^ xm;
        ulonglong2 v; v.x = X[k]; v.y = Y[k];
        sm2[idx] = v;
    }
}
template <int P>
__device__ __forceinline__ void ldR(const ulonglong2* sm2, int u, int s2, u64* X, u64* Y) {
#pragma unroll
    for (int k = 0; k < 16; k++) {
        const int idx = swz((cfg<P>(u, k) << 2) | s2);
        const ulonglong2 v = sm2[idx];
        X[k] = v.x; Y[k] = v.y;
    }
}

// ---------------- setup ----------------
__global__ void setup_kernel(const float* __restrict__ x,
                             const float* __restrict__ params) {
    int t = blockIdx.x * blockDim.x + threadIdx.x;
    if (t < 80) {
        // t = layer*20 + pass*10 + j ; wire = pass ? 19-j : 9-j
        int layer = t / 20, rest = t % 20, pass = rest / 10, j = rest % 10;
        int wire = pass ? (19 - j) : (9 - j);
        float phi = params[(layer * 20 + wire) * 3 + 0];
        float th  = params[(layer * 20 + wire) * 3 + 1];
        float om  = params[(layer * 20 + wire) * 3 + 2];
        float ct, st;  sincosf(0.5f * th, &st, &ct);
        float ap = -0.5f * (phi + om);
        float am =  0.5f * (phi - om);
        float ca, sa;  sincosf(ap, &sa, &ca);
        float cb, sb;  sincosf(am, &sb, &cb);
        // m00 = e^{i ap} ct ; m01 = -e^{i am} st ; m10 = -conj(m01) ; m11 = conj(m00)
        const float m00x = ca * ct, m00y = sa * ct;
        const float m01x = -cb * st, m01y = -sb * st;
        ulonglong2 q;
        q.x = dupf(m00x); q.y = dupf(m00y);  g_rotB[t * 4 + 0] = q;
        q.x = dupf(-m00y); q.y = dupf(m01x); g_rotB[t * 4 + 1] = q;
        q.x = dupf(-m01x); q.y = dupf(m01y); g_rotB[t * 4 + 2] = q;
        q.x = dupf(-m01y); q.y = 0;          g_rotB[t * 4 + 3] = q;
    }
    int v = t - 80;
    if (v >= 0 && v < 64 * 20) {
        float c, s;  sincosf(0.5f * x[v], &s, &c);
        g_cs[v] = make_float2(c, s);
    }
}

__device__ __forceinline__ float2 rxf(float2 v, float2 f, int bit) {
    if (bit) return make_float2(f.y * v.y, -f.y * v.x);
    return make_float2(f.x * v.x, f.x * v.y);
}

// ---------------- main pass kernel ----------------
// PASS: 0 = pass1 (reads A, writes B), 1 = pass2 (reads B, writes A).
// MODE: 0 normal, 1 GEN (layer0 pass1, no read), 2 RED (layer3 pass2, no write).
template <int PASS, int MODE>
__global__ void __launch_bounds__(256, 2) qpass(int layer, float* __restrict__ out) {
    extern __shared__ ulonglong2 sm2[];          // 4096 x 16B = 64KB
    const int t  = threadIdx.x;
    const int s2 = t & 3;            // sample-pair id (2 packed samples)
    const int u  = t >> 2;           // 6 bits: complement of window's 4 k-bits
    const int r  = blockIdx.x & 1023;
    const int sg = blockIdx.x >> 10;
    const float4* gin = (const float4*)(PASS == 0 ? g_A : g_B);
    float4* gout      = (float4*)(PASS == 0 ? g_B : g_A);
    const ulonglong2* rmB = g_rotB + (layer * 2 + PASS) * 40;

    u64 X[16], Y[16];
    u64 m[7];

    // ================= Window 1 (k_q <-> c_{6+q}) =================
    if (MODE == 1) {
        // Generate post-RX product state directly (layer0 pass1).
        const float2* csA = g_cs + (sg * 8 + s2 * 2) * 20;
        const float2* csB = csA + 20;
        float2 a0 = make_float2(1.f, 0.f), a1 = make_float2(1.f, 0.f);
#pragma unroll
        for (int p = 0; p < 10; p++) {      // i bits 0..9 (= r), wire 19-p
            const int b = (r >> p) & 1;
            a0 = rxf(a0, csA[19 - p], b);
            a1 = rxf(a1, csB[19 - p], b);
        }
#pragma unroll
        for (int j = 0; j < 6; j++) {       // c bits 0..5 (= u), wire 9-j
            const int b = (u >> j) & 1;
            a0 = rxf(a0, csA[9 - j], b);
            a1 = rxf(a1, csB[9 - j], b);
        }
#pragma unroll
        for (int k = 0; k < 16; k++) {      // k_q -> wire 3-q
            float2 w0 = a0, w1 = a1;
#pragma unroll
            for (int q = 0; q < 4; q++) {
                const int b = (k >> q) & 1;
                w0 = rxf(w0, csA[3 - q], b);
                w1 = rxf(w1, csB[3 - q], b);
            }
            X[k] = pk(w0.x, w1.x);
            Y[k] = pk(w0.y, w1.y);
        }
    } else {
        // Dense contiguous read: CTA block = (r*8+sg)*64KB, float4 granularity.
        const int base4 = (r * 8 + sg) * 4096;
#pragma unroll
        for (int k = 0; k < 16; k++) {
            const float4 v = __ldcs(gin + base4 + (((k << 6) | u) << 2) + s2);
            X[k] = pk(v.x, v.z);
            Y[k] = pk(v.y, v.w);
        }
    }
    ldm(rmB, 9, m); rotg<3>(X, Y, m);       // rot c9
    ldm(rmB, 8, m); rotg<2>(X, Y, m);       // rot c8
    ldm(rmB, 7, m); rotg<1>(X, Y, m);       // rot c7
    ldm(rmB, 6, m); rotg<0>(X, Y, m);       // rot c6
    // pass2: CNOT(9,10) = uniform flip of c9 (k3) before the chain; with the
    // (linear) chain folded, dest ^= permk(8)=15 -> idx mask 0xF00.
    const int xm = (PASS == 1 && (r & 1)) ? 0xF00 : 0;
    stR<6>(sm2, u, s2, X, Y, xm);           // CNOTs (c9,c8)(c8,c7)(c7,c6) folded
    __syncthreads();

    // ================= Window 2 (k_q <-> c_{3+q}) =================
    ldR<3>(sm2, u, s2, X, Y);
    ldm(rmB, 5, m); rotg<2>(X, Y, m);       // rot c5
    ldm(rmB, 4, m); rotg<1>(X, Y, m);       // rot c4
    ldm(rmB, 3, m); rotg<0>(X, Y, m);       // rot c3
    stR<3>(sm2, u, s2, X, Y, 0);            // CNOTs (c6,c5)(c5,c4)(c4,c3) folded
    __syncthreads();

    // ================= Window 3 (k_q <-> c_q) =================
    ldR<0>(sm2, u, s2, X, Y);
    ldm(rmB, 2, m); rotg<2>(X, Y, m);       // rot c2
    ldm(rmB, 1, m); rotg<1>(X, Y, m);       // rot c1
    ldm(rmB, 0, m); rotg<0>(X, Y, m);       // rot c0
    // CNOTs (c3,c2)(c2,c1)(c1,c0) folded into the output index / sign below.

    if (MODE == 2) {
        // <Z_0> with final CNOT(19,0) folded: sign = bit19 ^ bit0.
        // bit19 = r bit 9 ; bit0 = dest c bit0 = parity(k) = permk(k)&1.
        u64 ps = 0;
        const int sb = (r >> 9) & 1;
#pragma unroll
        for (int k = 0; k < 16; k++) {
            const u64 mag = f2fma(Y[k], Y[k], f2mul(X[k], X[k]));
            if (((permk(k) ^ sb) & 1) == 0) ps = f2add(ps, mag);
            else                            ps = f2sub(ps, mag);
        }
        ps = f2add(ps, __shfl_xor_sync(0xffffffffu, ps, 4));
        ps = f2add(ps, __shfl_xor_sync(0xffffffffu, ps, 8));
        ps = f2add(ps, __shfl_xor_sync(0xffffffffu, ps, 16));
        __syncthreads();                    // smem reuse barrier
        u64* smr = (u64*)sm2;
        const int lane = t & 31, wid = t >> 5;
        if (lane < 4) smr[wid * 4 + lane] = ps;
        __syncthreads();
        if (t < 4) {
            float2 acc = make_float2(0.f, 0.f);
#pragma unroll
            for (int w = 0; w < 8; w++) {
                const float2 q = up(smr[w * 4 + t]);
                acc.x += q.x; acc.y += q.y;
            }
            atomicAdd(out + sg * 8 + t * 2 + 0, acc.x);
            atomicAdd(out + sg * 8 + t * 2 + 1, acc.y);
        }
    } else {
        // Scatter-write into the other buffer's (next-pass-dense) layout.
        // pass2 additionally folds CNOT(19,0): dest bit19 (r bit9) ^= dest bit0.
#pragma unroll
        for (int k = 0; k < 16; k++) {
            const int c = (u << 4) | permk(k);
            const int rr = (PASS == 1) ? (r ^ ((c & 1) << 9)) : r;
            const int idx4 = c * 32768 + sg * 4096 + rr * 4 + s2;
            const float2 xx = up(X[k]);
            const float2 yy = up(Y[k]);
            __stcs(gout + idx4, make_float4(xx.x, yy.x, xx.y, yy.y));
        }
    }
}

// ---------------------------------------------------------------------------
extern "C" void kernel_launch(void* const* d_in, const int* in_sizes, int n_in,
                              void* d_out, int out_size) {
    const float* x      = (const float*)d_in[0];
    const float* params = (const float*)d_in[1];
    if (n_in >= 2 && in_sizes[0] == 240 && in_sizes[1] == 1280) {  // defensive swap
        const float* tmp = x; x = params; params = tmp;
    }
    float* out = (float*)d_out;

    const size_t SH = 4096 * sizeof(ulonglong2);   // 64 KB dynamic smem
    cudaFuncSetAttribute(qpass<0, 1>, cudaFuncAttributeMaxDynamicSharedMemorySize, (int)SH);
    cudaFuncSetAttribute(qpass<0, 0>, cudaFuncAttributeMaxDynamicSharedMemorySize, (int)SH);
    cudaFuncSetAttribute(qpass<1, 0>, cudaFuncAttributeMaxDynamicSharedMemorySize, (int)SH);
    cudaFuncSetAttribute(qpass<1, 2>, cudaFuncAttributeMaxDynamicSharedMemorySize, (int)SH);

    setup_kernel<<<6, 256>>>(x, params);

    const int GRID = 8192, TB = 256;
    qpass<0, 1><<<GRID, TB, SH>>>(0, nullptr);   // layer0 pass1: GEN -> B
    qpass<1, 0><<<GRID, TB, SH>>>(0, nullptr);   // B -> A
    for (int d = 1; d <= 2; d++) {
        qpass<0, 0><<<GRID, TB, SH>>>(d, nullptr);   // A -> B
        qpass<1, 0><<<GRID, TB, SH>>>(d, nullptr);   // B -> A
    }
    qpass<0, 0><<<GRID, TB, SH>>>(3, nullptr);       // A -> B
    cudaMemsetAsync(d_out, 0, (size_t)out_size * sizeof(float));
    qpass<1, 2><<<GRID, TB, SH>>>(3, out);           // layer3 pass2: RED (reads B)
}

// round 9
// speedup vs baseline: 2.3501x; 1.0287x over previous
#include <cuda_runtime.h>
#include <cstdint>

// ============================================================================
// 20-qubit depth-4 strongly-entangling circuit, batch 64, <Z_0>.
// 8 full-state sweeps, ping-pong A<->B; every pass READS a contiguous 64KB
// block per CTA, writes scattered 64B segments in the other buffer's layout.
//   buffer element (16B quad) = (Re_s0, Re_s1, Im_s0, Im_s1)  [ulonglong2:
//   .x = packed Re pair = X, .y = packed Im pair = Y]
//   buffer A (input of pass1): idx = r1*32768 + sg*4096 + c1*4 + s2
//   buffer B (input of pass2): idx = r2*32768 + sg*4096 + c2*4 + s2
// CNOT(19,0) folded into pass2's write base (even/odd d), CNOT(9,10) folded
// into pass2 W1 store offsets (d^15).  In-window CNOT chains folded statically
// into store indices (permk = prefix parity).  Rot: m11=conj(m00),
// m10=-conj(m01) -> 7 broadcast scalars, negations precomputed.
// All smem accesses are [base + compile-time-immediate]: the swizzle
// (idx ^ ((idx>>6&1)<<2)) is folded into per-window base pointers; in W3 a
// register relabel (reg k <-> cfg k^(u&1)) cancels it exactly.  Under that
// relabel, rot c0's |0>/|1> roles swap for u0=1 threads: the role-swapped
// matrix [[m11,m10],[m01,m00]] keeps the same conjugate structure
// (m00'=conj(m00), m01'=-conj(m01)) and is precomputed at table slot j=10.
// Streaming hints (__ldcs/__stcs).  2 __syncthreads per pass.
// ============================================================================

using u64 = unsigned long long;

#define NSTATE (1 << 20)

__device__ ulonglong2 g_A[(size_t)NSTATE * 32];      // 512 MB
__device__ ulonglong2 g_B[(size_t)NSTATE * 32];      // 512 MB
__device__ ulonglong2 g_rotB[4 * 2 * 11 * 4];        // j=0..9 rots, j=10 = swapped j=0
__device__ float2 g_cs[64 * 20];                     // (cos(x/2), sin(x/2)) per (s,w)

#define SGN 0x8000000080000000ULL

// ---------------- packed f32x2 helpers ----------------
__device__ __forceinline__ u64 f2mul(u64 a, u64 b) {
    u64 d; asm("mul.rn.f32x2 %0,%1,%2;" : "=l"(d) : "l"(a), "l"(b)); return d;
}
__device__ __forceinline__ u64 f2fma(u64 a, u64 b, u64 c) {
    u64 d; asm("fma.rn.f32x2 %0,%1,%2,%3;" : "=l"(d) : "l"(a), "l"(b), "l"(c)); return d;
}
__device__ __forceinline__ u64 f2add(u64 a, u64 b) {
    u64 d; asm("add.rn.f32x2 %0,%1,%2;" : "=l"(d) : "l"(a), "l"(b)); return d;
}
__device__ __forceinline__ u64 pk(float lo, float hi) {
    u64 d; asm("mov.b64 %0, {%1, %2};" : "=l"(d) : "f"(lo), "f"(hi)); return d;
}
__device__ __forceinline__ float2 up(u64 a) {
    float2 r; asm("mov.b64 {%0, %1}, %2;" : "=f"(r.x), "=f"(r.y) : "l"(a)); return r;
}
__device__ __forceinline__ u64 dupf(float v) {
    unsigned b = __float_as_uint(v); return (u64)b | ((u64)b << 32);
}

// ---------------- static CNOT-chain permutation (prefix parity) ----------------
// chain (k3,k2)(k2,k1)(k1,k0): d3=k3, d2=k2^k3, d1=k1^k2^k3, d0=k0^k1^k2^k3
__device__ __forceinline__ constexpr int permk(int k) {
    int p3 = (k >> 3) & 1;
    int p2 = ((k >> 2) & 1) ^ p3;
    int p1 = ((k >> 1) & 1) ^ p2;
    int p0 = (k & 1) ^ p1;
    return (p3 << 3) | (p2 << 2) | (p1 << 1) | p0;
}

// ---------------- Rot on 16-config register block ----------------
// m: {m00x, m00y, -m00y, m01x, -m01x, m01y, -m01y} broadcast in f32x2 pairs.
template <int Q>
__device__ __forceinline__ void rotg(u64* X, u64* Y, const u64* m) {
#pragma unroll
    for (int k = 0; k < 16; k++) {
        if (k & (1 << Q)) continue;
        const int k1 = k | (1 << Q);
        const u64 aX = X[k], aY = Y[k], bX = X[k1], bY = Y[k1];
        X[k]  = f2fma(m[6], bY, f2fma(m[3], bX, f2fma(m[2], aY, f2mul(m[0], aX))));
        Y[k]  = f2fma(m[5], bX, f2fma(m[3], bY, f2fma(m[1], aX, f2mul(m[0], aY))));
        X[k1] = f2fma(m[1], bY, f2fma(m[0], bX, f2fma(m[6], aY, f2mul(m[4], aX))));
        Y[k1] = f2fma(m[2], bX, f2fma(m[0], bY, f2fma(m[5], aX, f2mul(m[4], aY))));
    }
}

__device__ __forceinline__ void ldm(const ulonglong2* rmB, int j, u64* m) {
    const ulonglong2 q0 = rmB[j * 4 + 0], q1 = rmB[j * 4 + 1];
    const ulonglong2 q2 = rmB[j * 4 + 2], q3 = rmB[j * 4 + 3];
    m[0] = q0.x; m[1] = q0.y; m[2] = q1.x; m[3] = q1.y;
    m[4] = q2.x; m[5] = q2.y; m[6] = q3.x;
}

// ---------------- setup ----------------
__global__ void setup_kernel(const float* __restrict__ x,
                             const float* __restrict__ params) {
    int t = blockIdx.x * blockDim.x + threadIdx.x;
    if (t < 80) {
        // t = layer*20 + pass*10 + j ; wire = pass ? 19-j : 9-j
        int layer = t / 20, rest = t % 20, pass = rest / 10, j = rest % 10;
        int wire = pass ? (19 - j) : (9 - j);
        float phi = params[(layer * 20 + wire) * 3 + 0];
        float th  = params[(layer * 20 + wire) * 3 + 1];
        float om  = params[(layer * 20 + wire) * 3 + 2];
        float ct, st;  sincosf(0.5f * th, &st, &ct);
        float ap = -0.5f * (phi + om);
        float am =  0.5f * (phi - om);
        float ca, sa;  sincosf(ap, &sa, &ca);
        float cb, sb;  sincosf(am, &sb, &cb);
        // m00 = e^{i ap} ct ; m01 = -e^{i am} st ; m10 = -conj(m01) ; m11 = conj(m00)
        const float m00x = ca * ct, m00y = sa * ct;
        const float m01x = -cb * st, m01y = -sb * st;
        ulonglong2* blk = g_rotB + (layer * 2 + pass) * 44;
        ulonglong2 q;
        q.x = dupf(m00x); q.y = dupf(m00y);  blk[j * 4 + 0] = q;
        q.x = dupf(-m00y); q.y = dupf(m01x); blk[j * 4 + 1] = q;
        q.x = dupf(-m01x); q.y = dupf(m01y); blk[j * 4 + 2] = q;
        q.x = dupf(-m01y); q.y = 0;          blk[j * 4 + 3] = q;
        if (j == 0) {
            // Role-swapped variant for W3's relabeled rot c0 (u0=1 threads):
            // matrix [[m11,m10],[m01,m00]] -> m00'=(m00x,-m00y), m01'=(-m01x,m01y)
            q.x = dupf(m00x); q.y = dupf(-m00y);  blk[10 * 4 + 0] = q;
            q.x = dupf(m00y); q.y = dupf(-m01x);  blk[10 * 4 + 1] = q;
            q.x = dupf(m01x); q.y = dupf(m01y);   blk[10 * 4 + 2] = q;
            q.x = dupf(-m01y); q.y = 0;           blk[10 * 4 + 3] = q;
        }
    }
    int v = t - 80;
    if (v >= 0 && v < 64 * 20) {
        float c, s;  sincosf(0.5f * x[v], &s, &c);
        g_cs[v] = make_float2(c, s);
    }
}

__device__ __forceinline__ float2 rxf(float2 v, float2 f, int bit) {
    if (bit) return make_float2(f.y * v.y, -f.y * v.x);
    return make_float2(f.x * v.x, f.x * v.y);
}

// ---------------- main pass kernel ----------------
// PASS: 0 = pass1 (reads A, writes B), 1 = pass2 (reads B, writes A).
// MODE: 0 normal, 1 GEN (layer0 pass1, no read), 2 RED (layer3 pass2, no write).
template <int PASS, int MODE>
__global__ void __launch_bounds__(256, 2) qpass(int layer, float* __restrict__ out) {
    extern __shared__ ulonglong2 sm2[];          // 4096 x 16B = 64KB
    const int t  = threadIdx.x;
    const int s2 = t & 3;            // sample-pair id (2 packed samples)
    const int u  = t >> 2;           // 6 bits: complement of window's 4 k-bits
    const int u0 = u & 1;
    const int r  = blockIdx.x & 1023;
    const int sg = blockIdx.x >> 10;
    const ulonglong2* gin = (PASS == 0 ? g_A : g_B);
    ulonglong2* gout      = (PASS == 0 ? g_B : g_A);
    const ulonglong2* rmB = g_rotB + (layer * 2 + PASS) * 44;

    u64 X[16], Y[16];
    u64 m[7];

    // ================= Window 1 (k_q <-> c_{6+q}) =================
    if (MODE == 1) {
        // Generate post-RX product state directly (layer0 pass1).
        const float2* csA = g_cs + (sg * 8 + s2 * 2) * 20;
        const float2* csB = csA + 20;
        float2 a0 = make_float2(1.f, 0.f), a1 = make_float2(1.f, 0.f);
#pragma unroll
        for (int p = 0; p < 10; p++) {      // i bits 0..9 (= r), wire 19-p
            const int b = (r >> p) & 1;
            a0 = rxf(a0, csA[19 - p], b);
            a1 = rxf(a1, csB[19 - p], b);
        }
#pragma unroll
        for (int j = 0; j < 6; j++) {       // c bits 0..5 (= u), wire 9-j
            const int b = (u >> j) & 1;
            a0 = rxf(a0, csA[9 - j], b);
            a1 = rxf(a1, csB[9 - j], b);
        }
#pragma unroll
        for (int k = 0; k < 16; k++) {      // k_q -> wire 3-q
            float2 w0 = a0, w1 = a1;
#pragma unroll
            for (int q = 0; q < 4; q++) {
                const int b = (k >> q) & 1;
                w0 = rxf(w0, csA[3 - q], b);
                w1 = rxf(w1, csB[3 - q], b);
            }
            X[k] = pk(w0.x, w1.x);
            Y[k] = pk(w0.y, w1.y);
        }
    } else {
        // Dense contiguous read: CTA block = (r*8+sg)*64KB; per-k immediates.
        const ulonglong2* gi = gin + (size_t)(r * 8 + sg) * 4096 + ((u << 2) | s2);
#pragma unroll
        for (int k = 0; k < 16; k++) {
            const ulonglong2 v = __ldcs(gi + (k << 8));
            X[k] = v.x;
            Y[k] = v.y;
        }
    }
    // rots commute: Q0 first so FFMAs start after the first loads land.
    ldm(rmB, 6, m); rotg<0>(X, Y, m);       // rot c6
    ldm(rmB, 7, m); rotg<1>(X, Y, m);       // rot c7
    ldm(rmB, 8, m); rotg<2>(X, Y, m);       // rot c8
    ldm(rmB, 9, m); rotg<3>(X, Y, m);       // rot c9
    // W1 store: idx16 = (d<<8)|(u<<2)|s2, swizzle bit6 = u bit4 -> base fold.
    {
        ulonglong2* pW1 = sm2 + ((((u << 2) | s2)) ^ (((u >> 4) & 1) << 2));
        // pass2: CNOT(9,10) flips c9(k3) pre-chain -> chain-folded dest d^15.
        if (PASS == 1 && (r & 1)) {
#pragma unroll
            for (int k = 0; k < 16; k++) {
                ulonglong2 v; v.x = X[k]; v.y = Y[k];
                pW1[(permk(k) ^ 15) << 8] = v;   // CNOTs (c9,c8)(c8,c7)(c7,c6)
            }
        } else {
#pragma unroll
            for (int k = 0; k < 16; k++) {
                ulonglong2 v; v.x = X[k]; v.y = Y[k];
                pW1[permk(k) << 8] = v;
            }
        }
    }
    __syncthreads();

    // ================= Window 2 (k_q <-> c_{3+q}) =================
    // idx16 = ((u>>3)<<9)|(k<<5)|((u&7)<<2)|s2, swizzle bit6 = k bit1 ->
    // compile-time select between base and base^4.
    {
        const int bw2 = (((u >> 3) << 9) | ((u & 7) << 2) | s2);
        ulonglong2* pA = sm2 + bw2;
        ulonglong2* pB = sm2 + (bw2 ^ 4);
#pragma unroll
        for (int k = 0; k < 16; k++) {
            const ulonglong2 v = (((k >> 1) & 1) ? pB : pA)[k << 5];
            X[k] = v.x; Y[k] = v.y;
        }
        ldm(rmB, 3, m); rotg<0>(X, Y, m);   // rot c3
        ldm(rmB, 4, m); rotg<1>(X, Y, m);   // rot c4
        ldm(rmB, 5, m); rotg<2>(X, Y, m);   // rot c5
        // same per-thread address set as the load -> no barrier in between
#pragma unroll
        for (int k = 0; k < 16; k++) {
            const int d = permk(k);          // CNOTs (c6,c5)(c5,c4)(c4,c3)
            ulonglong2 v; v.x = X[k]; v.y = Y[k];
            (((d >> 1) & 1) ? pB : pA)[d << 5] = v;
        }
    }
    __syncthreads();

    // ================= Window 3 (k_q <-> c_q), reg relabel k <-> cfg k^u0 ====
    // idx16 = (u<<6)|(cfg<<2)|s2, swizzle bit6 = u bit0; with cfg = k^u0 the
    // swizzle cancels: addr = (u<<6)|s2 + (k<<2).  Register k holds cfg k^u0.
    {
        const ulonglong2* pW3 = sm2 + ((u << 6) | s2);
#pragma unroll
        for (int k = 0; k < 16; k++) {
            const ulonglong2 v = pW3[k << 2];
            X[k] = v.x; Y[k] = v.y;
        }
    }
    // rot c0 under the relabel: u0=1 threads need the role-swapped matrix
    // (precomputed at table slot j=10); u0=0 threads use the normal slot j=0.
    ldm(rmB, u0 ? 10 : 0, m); rotg<0>(X, Y, m);   // rot c0
    ldm(rmB, 1, m); rotg<1>(X, Y, m);             // rot c1
    ldm(rmB, 2, m); rotg<2>(X, Y, m);             // rot c2
    // CNOTs (c3,c2)(c2,c1)(c1,c0): dest cfg = permk(k^u0) = permk(k)^u0.

    if (MODE == 2) {
        // <Z_0> with final CNOT(19,0) folded: sign = bit19 ^ bit0.
        // bit19 = r bit 9 ; bit0 = dest cfg bit0 = (permk(k)^u0)&1.
        const int sbx = (((r >> 9) & 1) ^ u0);
        const u64 mA = sbx ? SGN : 0;        // mask when permk(k)&1 == 0
        const u64 mB = mA ^ SGN;             // mask when permk(k)&1 == 1
        u64 ps = 0;
#pragma unroll
        for (int k = 0; k < 16; k++) {
            u64 mag = f2fma(Y[k], Y[k], f2mul(X[k], X[k]));
            mag ^= (permk(k) & 1) ? mB : mA;
            ps = f2add(ps, mag);
        }
        ps = f2add(ps, __shfl_xor_sync(0xffffffffu, ps, 4));
        ps = f2add(ps, __shfl_xor_sync(0xffffffffu, ps, 8));
        ps = f2add(ps, __shfl_xor_sync(0xffffffffu, ps, 16));
        __syncthreads();                    // smem reuse barrier
        u64* smr = (u64*)sm2;
        const int lane = t & 31, wid = t >> 5;
        if (lane < 4) smr[wid * 4 + lane] = ps;
        __syncthreads();
        if (t < 4) {
            float2 acc = make_float2(0.f, 0.f);
#pragma unroll
            for (int w = 0; w < 8; w++) {
                const float2 q = up(smr[w * 4 + t]);
                acc.x += q.x; acc.y += q.y;
            }
            atomicAdd(out + sg * 8 + t * 2 + 0, acc.x);
            atomicAdd(out + sg * 8 + t * 2 + 1, acc.y);
        }
    } else {
        // Scatter-write into the other buffer's (next-pass-dense) layout.
        // global c = (u<<4)|(permk(k)^u0).  pass2 folds CNOT(19,0):
        // dest r bit9 ^= c bit0 -> even/odd-d base pointers.
        const size_t cb = (size_t)(u << 4) * 32768 + sg * 4096 + s2;
        ulonglong2* goE = gout + cb + r * 4;
        ulonglong2* goO = (PASS == 1) ? (gout + cb + (r ^ 512) * 4)
                                      : goE;
#pragma unroll
        for (int k = 0; k < 16; k++) {
            const int d = permk(k) ^ u0;     // runtime: 1 XOR (u0 per-thread)
            ulonglong2 v; v.x = X[k]; v.y = Y[k];
            __stcs(((d & 1) ? goO : goE) + d * 32768, v);
        }
    }
}

// ---------------------------------------------------------------------------
extern "C" void kernel_launch(void* const* d_in, const int* in_sizes, int n_in,
                              void* d_out, int out_size) {
    const float* x      = (const float*)d_in[0];
    const float* params = (const float*)d_in[1];
    if (n_in >= 2 && in_sizes[0] == 240 && in_sizes[1] == 1280) {  // defensive swap
        const float* tmp = x; x = params; params = tmp;
    }
    float* out = (float*)d_out;

    const size_t SH = 4096 * sizeof(ulonglong2);   // 64 KB dynamic smem
    cudaFuncSetAttribute(qpass<0, 1>, cudaFuncAttributeMaxDynamicSharedMemorySize, (int)SH);
    cudaFuncSetAttribute(qpass<0, 0>, cudaFuncAttributeMaxDynamicSharedMemorySize, (int)SH);
    cudaFuncSetAttribute(qpass<1, 0>, cudaFuncAttributeMaxDynamicSharedMemorySize, (int)SH);
    cudaFuncSetAttribute(qpass<1, 2>, cudaFuncAttributeMaxDynamicSharedMemorySize, (int)SH);

    setup_kernel<<<6, 256>>>(x, params);

    const int GRID = 8192, TB = 256;
    qpass<0, 1><<<GRID, TB, SH>>>(0, nullptr);   // layer0 pass1: GEN -> B
    qpass<1, 0><<<GRID, TB, SH>>>(0, nullptr);   // B -> A
    for (int d = 1; d <= 2; d++) {
        qpass<0, 0><<<GRID, TB, SH>>>(d, nullptr);   // A -> B
        qpass<1, 0><<<GRID, TB, SH>>>(d, nullptr);   // B -> A
    }
    qpass<0, 0><<<GRID, TB, SH>>>(3, nullptr);       // A -> B
    cudaMemsetAsync(d_out, 0, (size_t)out_size * sizeof(float));
    qpass<1, 2><<<GRID, TB, SH>>>(3, out);           // layer3 pass2: RED (reads B)
}